// round 1
// baseline (speedup 1.0000x reference)
#include <cuda_runtime.h>
#include <cstdint>

#define BATCH   65536
#define DIM     128
#define NEG     5
#define WARPS_PER_BLOCK 8
#define THREADS (WARPS_PER_BLOCK * 32)

__global__ void init_out_kernel(float* out) {
    if (threadIdx.x == 0) out[0] = 0.0f;
}

__device__ __forceinline__ float warp_sum(float v) {
#pragma unroll
    for (int o = 16; o > 0; o >>= 1)
        v += __shfl_xor_sync(0xffffffffu, v, o);
    return v;
}

// -log_sigmoid(x) = log(1+exp(-x)) = max(-x, 0) + log1p(exp(-|x|))
__device__ __forceinline__ float neg_log_sigmoid(float x) {
    return fmaxf(-x, 0.0f) + log1pf(__expf(-fabsf(x)));
}

__global__ __launch_bounds__(THREADS)
void skipgram_loss_kernel(const float* __restrict__ u_w,
                          const float* __restrict__ v_w,
                          const int*   __restrict__ pos_u,
                          const int*   __restrict__ pos_v,
                          const int*   __restrict__ neg_v,
                          float* __restrict__ out) {
    const int warp_global = (blockIdx.x * THREADS + threadIdx.x) >> 5;
    const int lane = threadIdx.x & 31;
    const int wid  = threadIdx.x >> 5;

    float loss = 0.0f;

    if (warp_global < BATCH) {
        const int b = warp_global;

        // indices (uniform per warp; L1 broadcast)
        const int64_t iu = pos_u[b];
        const int64_t iv = pos_v[b];
        int64_t ineg[NEG];
#pragma unroll
        for (int k = 0; k < NEG; k++) ineg[k] = neg_v[b * NEG + k];

        // issue all 7 row loads back-to-back for MLP
        const float4 u4 = *reinterpret_cast<const float4*>(u_w + iu * DIM + lane * 4);
        float4 v4[NEG + 1];
        v4[0] = *reinterpret_cast<const float4*>(v_w + iv * DIM + lane * 4);
#pragma unroll
        for (int k = 0; k < NEG; k++)
            v4[k + 1] = *reinterpret_cast<const float4*>(v_w + ineg[k] * DIM + lane * 4);

        // per-lane partial dots, then warp reductions
        float dots[NEG + 1];
#pragma unroll
        for (int j = 0; j < NEG + 1; j++) {
            float d = u4.x * v4[j].x;
            d = fmaf(u4.y, v4[j].y, d);
            d = fmaf(u4.z, v4[j].z, d);
            d = fmaf(u4.w, v4[j].w, d);
            dots[j] = warp_sum(d);
        }

        // positive term
        float s = fminf(fmaxf(dots[0], -10.0f), 10.0f);
        loss = neg_log_sigmoid(s);
        // negative terms: -log_sigmoid(-ns)
#pragma unroll
        for (int k = 1; k < NEG + 1; k++) {
            float ns = fminf(fmaxf(dots[k], -10.0f), 10.0f);
            loss += neg_log_sigmoid(-ns);
        }
    }

    // block reduction (every lane of a warp holds the same full value; take lane 0)
    __shared__ float smem[WARPS_PER_BLOCK];
    if (lane == 0) smem[wid] = loss;
    __syncthreads();

    if (threadIdx.x == 0) {
        float blk = 0.0f;
#pragma unroll
        for (int i = 0; i < WARPS_PER_BLOCK; i++) blk += smem[i];
        // BATCH = 2^16 -> exact scaling; no-return atomicAdd lowers to REDG
        atomicAdd(out, blk * (1.0f / (float)BATCH));
    }
}

extern "C" void kernel_launch(void* const* d_in, const int* in_sizes, int n_in,
                              void* d_out, int out_size) {
    const float* u_w   = (const float*)d_in[0];
    const float* v_w   = (const float*)d_in[1];
    const int*   pos_u = (const int*)d_in[2];
    const int*   pos_v = (const int*)d_in[3];
    const int*   neg_v = (const int*)d_in[4];
    float* out = (float*)d_out;

    init_out_kernel<<<1, 32>>>(out);

    const int total_warps = BATCH;
    const int blocks = (total_warps + WARPS_PER_BLOCK - 1) / WARPS_PER_BLOCK;
    skipgram_loss_kernel<<<blocks, THREADS>>>(u_w, v_w, pos_u, pos_v, neg_v, out);
}